// round 9
// baseline (speedup 1.0000x reference)
#include <cuda_runtime.h>
#include <math.h>

#define BATCH 2
#define SEQ   2048
#define EMB   1024
#define NHEAD 16
#define HDIM  64
#define NEGF  1e30f

// Scratch (allocation-free rule: __device__ globals)
__device__ float g_Q[BATCH * NHEAD * SEQ * HDIM];   // [B,H,S,D]
__device__ float g_K[BATCH * NHEAD * SEQ * HDIM];   // [B,H,S,D]
__device__ float g_V[BATCH * NHEAD * SEQ * HDIM];   // [B,H,S,D]
__device__ float g_A[BATCH * SEQ * EMB];            // [B,S,H*D]

// ============================================================================
// GEMM-NT 128x128x16, 256 threads, 8x8 per-thread tile, double-buffered smem
// with register prefetch: ONE __syncthreads per K-chunk.
// C[m][n] = sum_k A[m][k] * B[n][k]   (A row-major [M,K], B row-major [N,K])
// ============================================================================

// ---- QKV projection: X[4096,1024] @ Wqkv[3072,1024]^T + b, scatter to Q/K/V
__global__ __launch_bounds__(256)
void qkv_gemm_kernel(const float* __restrict__ X,
                     const float* __restrict__ W,
                     const float* __restrict__ bias)
{
    __shared__ float As[2][16][132];
    __shared__ float Bs[2][16][132];
    const int tid = threadIdx.x;
    const int tx = tid & 15, ty = tid >> 4;
    const int bm = blockIdx.y * 128, bn = blockIdx.x * 128;
    const int lrow = tid >> 2;
    const int lc4  = (tid & 3) << 2;

    float acc[8][8];
    #pragma unroll
    for (int i = 0; i < 8; i++)
        #pragma unroll
        for (int j = 0; j < 8; j++) acc[i][j] = 0.f;

    const float* pA0 = X + (size_t)(bm + lrow) * EMB + lc4;
    const float* pA1 = X + (size_t)(bm + lrow + 64) * EMB + lc4;
    const float* pB0 = W + (size_t)(bn + lrow) * EMB + lc4;
    const float* pB1 = W + (size_t)(bn + lrow + 64) * EMB + lc4;

    float4 ra0 = *(const float4*)pA0;
    float4 ra1 = *(const float4*)pA1;
    float4 rb0 = *(const float4*)pB0;
    float4 rb1 = *(const float4*)pB1;

    #pragma unroll 1
    for (int c = 0; c < EMB / 16; c++) {
        const int buf = c & 1;
        As[buf][lc4 + 0][lrow] = ra0.x; As[buf][lc4 + 1][lrow] = ra0.y;
        As[buf][lc4 + 2][lrow] = ra0.z; As[buf][lc4 + 3][lrow] = ra0.w;
        As[buf][lc4 + 0][lrow + 64] = ra1.x; As[buf][lc4 + 1][lrow + 64] = ra1.y;
        As[buf][lc4 + 2][lrow + 64] = ra1.z; As[buf][lc4 + 3][lrow + 64] = ra1.w;
        Bs[buf][lc4 + 0][lrow] = rb0.x; Bs[buf][lc4 + 1][lrow] = rb0.y;
        Bs[buf][lc4 + 2][lrow] = rb0.z; Bs[buf][lc4 + 3][lrow] = rb0.w;
        Bs[buf][lc4 + 0][lrow + 64] = rb1.x; Bs[buf][lc4 + 1][lrow + 64] = rb1.y;
        Bs[buf][lc4 + 2][lrow + 64] = rb1.z; Bs[buf][lc4 + 3][lrow + 64] = rb1.w;
        __syncthreads();

        if (c + 1 < EMB / 16) {
            const int o = (c + 1) * 16;
            ra0 = *(const float4*)(pA0 + o);
            ra1 = *(const float4*)(pA1 + o);
            rb0 = *(const float4*)(pB0 + o);
            rb1 = *(const float4*)(pB1 + o);
        }

        #pragma unroll
        for (int k = 0; k < 16; k++) {
            float4 a0 = *(const float4*)&As[buf][k][ty * 4];
            float4 a1 = *(const float4*)&As[buf][k][64 + ty * 4];
            float4 b0 = *(const float4*)&Bs[buf][k][tx * 4];
            float4 b1 = *(const float4*)&Bs[buf][k][64 + tx * 4];
            float a[8] = {a0.x, a0.y, a0.z, a0.w, a1.x, a1.y, a1.z, a1.w};
            float b[8] = {b0.x, b0.y, b0.z, b0.w, b1.x, b1.y, b1.z, b1.w};
            #pragma unroll
            for (int i = 0; i < 8; i++)
                #pragma unroll
                for (int j = 0; j < 8; j++)
                    acc[i][j] += a[i] * b[j];
        }
    }

    #pragma unroll
    for (int i = 0; i < 8; i++) {
        int m = bm + ((i < 4) ? (ty * 4 + i) : (64 + ty * 4 + i - 4));
        int bb = m >> 11;
        int ss = m & (SEQ - 1);
        #pragma unroll
        for (int j = 0; j < 8; j++) {
            int n = bn + ((j < 4) ? (tx * 4 + j) : (64 + tx * 4 + j - 4));
            float v = acc[i][j] + bias[n];
            int w = n >> 10;
            int h = (n >> 6) & 15;
            int d = n & 63;
            float* dst = (w == 0) ? g_Q : (w == 1) ? g_K : g_V;
            dst[(((size_t)(bb * NHEAD + h)) * SEQ + ss) * HDIM + d] = v;
        }
    }
}

// ---- Output projection: A[4096,1024] @ Wo[1024,1024]^T + b -> out
__global__ __launch_bounds__(256)
void out_gemm_kernel(const float* __restrict__ W,
                     const float* __restrict__ bias,
                     float* __restrict__ out)
{
    __shared__ float As[2][16][132];
    __shared__ float Bs[2][16][132];
    const int tid = threadIdx.x;
    const int tx = tid & 15, ty = tid >> 4;
    const int bm = blockIdx.y * 128, bn = blockIdx.x * 128;
    const int lrow = tid >> 2;
    const int lc4  = (tid & 3) << 2;

    float acc[8][8];
    #pragma unroll
    for (int i = 0; i < 8; i++)
        #pragma unroll
        for (int j = 0; j < 8; j++) acc[i][j] = 0.f;

    const float* pA0 = g_A + (size_t)(bm + lrow) * EMB + lc4;
    const float* pA1 = g_A + (size_t)(bm + lrow + 64) * EMB + lc4;
    const float* pB0 = W + (size_t)(bn + lrow) * EMB + lc4;
    const float* pB1 = W + (size_t)(bn + lrow + 64) * EMB + lc4;

    float4 ra0 = *(const float4*)pA0;
    float4 ra1 = *(const float4*)pA1;
    float4 rb0 = *(const float4*)pB0;
    float4 rb1 = *(const float4*)pB1;

    #pragma unroll 1
    for (int c = 0; c < EMB / 16; c++) {
        const int buf = c & 1;
        As[buf][lc4 + 0][lrow] = ra0.x; As[buf][lc4 + 1][lrow] = ra0.y;
        As[buf][lc4 + 2][lrow] = ra0.z; As[buf][lc4 + 3][lrow] = ra0.w;
        As[buf][lc4 + 0][lrow + 64] = ra1.x; As[buf][lc4 + 1][lrow + 64] = ra1.y;
        As[buf][lc4 + 2][lrow + 64] = ra1.z; As[buf][lc4 + 3][lrow + 64] = ra1.w;
        Bs[buf][lc4 + 0][lrow] = rb0.x; Bs[buf][lc4 + 1][lrow] = rb0.y;
        Bs[buf][lc4 + 2][lrow] = rb0.z; Bs[buf][lc4 + 3][lrow] = rb0.w;
        Bs[buf][lc4 + 0][lrow + 64] = rb1.x; Bs[buf][lc4 + 1][lrow + 64] = rb1.y;
        Bs[buf][lc4 + 2][lrow + 64] = rb1.z; Bs[buf][lc4 + 3][lrow + 64] = rb1.w;
        __syncthreads();

        if (c + 1 < EMB / 16) {
            const int o = (c + 1) * 16;
            ra0 = *(const float4*)(pA0 + o);
            ra1 = *(const float4*)(pA1 + o);
            rb0 = *(const float4*)(pB0 + o);
            rb1 = *(const float4*)(pB1 + o);
        }

        #pragma unroll
        for (int k = 0; k < 16; k++) {
            float4 a0 = *(const float4*)&As[buf][k][ty * 4];
            float4 a1 = *(const float4*)&As[buf][k][64 + ty * 4];
            float4 b0 = *(const float4*)&Bs[buf][k][tx * 4];
            float4 b1 = *(const float4*)&Bs[buf][k][64 + tx * 4];
            float a[8] = {a0.x, a0.y, a0.z, a0.w, a1.x, a1.y, a1.z, a1.w};
            float b[8] = {b0.x, b0.y, b0.z, b0.w, b1.x, b1.y, b1.z, b1.w};
            #pragma unroll
            for (int i = 0; i < 8; i++)
                #pragma unroll
                for (int j = 0; j < 8; j++)
                    acc[i][j] += a[i] * b[j];
        }
    }

    #pragma unroll
    for (int i = 0; i < 8; i++) {
        int m = bm + ((i < 4) ? (ty * 4 + i) : (64 + ty * 4 + i - 4));
        #pragma unroll
        for (int j = 0; j < 8; j++) {
            int n = bn + ((j < 4) ? (tx * 4 + j) : (64 + tx * 4 + j - 4));
            out[(size_t)m * EMB + n] = acc[i][j] + bias[n];
        }
    }
}

// ============================================================================
// Flash attention, causal, fp32. Block = 64 queries; key tiles of 32.
// 256 threads as 16x16; per-thread: S tile 4x2 (cols tx, tx+16), O tile 4x4.
// Online-softmax state (m,l) lives in REGISTERS, replicated across each
// 16-thread row group; row reductions via 4-step shfl_xor (offs 1,2,4,8).
// ============================================================================
__global__ __launch_bounds__(256)
void attn_kernel(const float* __restrict__ ghost)
{
    __shared__ float Qs[64][68];
    __shared__ float Ks[32][68];
    __shared__ float Vs[32][68];
    __shared__ float Ss[64][33];

    const int qi = blockIdx.x;          // 0..31
    const int bh = blockIdx.y;          // 0..31
    const int tid = threadIdx.x;
    const int tx = tid & 15, ty = tid >> 4;
    const int r0 = ty * 4;
    const int q0 = qi * 64;

    const float* Qb = g_Q + (size_t)bh * SEQ * HDIM;
    const float* Kb = g_K + (size_t)bh * SEQ * HDIM;
    const float* Vb = g_V + (size_t)bh * SEQ * HDIM;

    for (int i = tid; i < 64 * 16; i += 256) {
        int r = i >> 4, c4 = (i & 15) << 2;
        *(float4*)&Qs[r][c4] = *(const float4*)&Qb[(size_t)(q0 + r) * HDIM + c4];
    }

    float acc[4][4];
    float rm[4], rl[4];
    #pragma unroll
    for (int i = 0; i < 4; i++) {
        rm[i] = -NEGF; rl[i] = 0.f;
        #pragma unroll
        for (int j = 0; j < 4; j++) acc[i][j] = 0.f;
    }

    __syncthreads();

    const int nkt = 2 * qi + 2;
    #pragma unroll 1
    for (int kt = 0; kt < nkt; kt++) {
        const int k0 = kt * 32;
        for (int i = tid; i < 32 * 16; i += 256) {
            int r = i >> 4, c4 = (i & 15) << 2;
            *(float4*)&Ks[r][c4] = *(const float4*)&Kb[(size_t)(k0 + r) * HDIM + c4];
            *(float4*)&Vs[r][c4] = *(const float4*)&Vb[(size_t)(k0 + r) * HDIM + c4];
        }
        __syncthreads();

        // S = Q K^T * 1/8 ; this thread: rows r0..r0+3, cols tx and tx+16
        float s[4][2] = {{0.f,0.f},{0.f,0.f},{0.f,0.f},{0.f,0.f}};
        #pragma unroll
        for (int d4 = 0; d4 < 64; d4 += 4) {
            float4 kv0 = *(const float4*)&Ks[tx][d4];
            float4 kv1 = *(const float4*)&Ks[tx + 16][d4];
            #pragma unroll
            for (int i = 0; i < 4; i++) {
                float4 qv = *(const float4*)&Qs[r0 + i][d4];
                s[i][0] += qv.x * kv0.x + qv.y * kv0.y + qv.z * kv0.z + qv.w * kv0.w;
                s[i][1] += qv.x * kv1.x + qv.y * kv1.y + qv.z * kv1.z + qv.w * kv1.w;
            }
        }
        const bool need_mask = (kt >= 2 * qi);
        #pragma unroll
        for (int i = 0; i < 4; i++) {
            int qq = q0 + r0 + i;
            #pragma unroll
            for (int j = 0; j < 2; j++) {
                int kk = k0 + tx + 16 * j;
                float v = s[i][j] * 0.125f;
                if (need_mask && kk > qq) v = -NEGF;
                s[i][j] = v;
            }
        }

        // register online softmax; row group = 16 lanes (same ty, half-warp)
        float sc[4];
        #pragma unroll
        for (int i = 0; i < 4; i++) {
            float t = fmaxf(s[i][0], s[i][1]);
            t = fmaxf(t, __shfl_xor_sync(0xffffffffu, t, 1));
            t = fmaxf(t, __shfl_xor_sync(0xffffffffu, t, 2));
            t = fmaxf(t, __shfl_xor_sync(0xffffffffu, t, 4));
            t = fmaxf(t, __shfl_xor_sync(0xffffffffu, t, 8));
            float mn = fmaxf(rm[i], t);
            sc[i] = __expf(rm[i] - mn);
            rm[i] = mn;
            float p0 = __expf(s[i][0] - mn);
            float p1 = __expf(s[i][1] - mn);
            float ps = p0 + p1;
            ps += __shfl_xor_sync(0xffffffffu, ps, 1);
            ps += __shfl_xor_sync(0xffffffffu, ps, 2);
            ps += __shfl_xor_sync(0xffffffffu, ps, 4);
            ps += __shfl_xor_sync(0xffffffffu, ps, 8);
            rl[i] = rl[i] * sc[i] + ps;
            Ss[r0 + i][tx] = p0;
            Ss[r0 + i][tx + 16] = p1;
        }
        __syncthreads();

        // O = O*sc + P @ V ; per-thread dims d0 = 4*tx
        const int d0 = tx * 4;
        #pragma unroll
        for (int i = 0; i < 4; i++) {
            float a0 = acc[i][0] * sc[i], a1 = acc[i][1] * sc[i];
            float a2 = acc[i][2] * sc[i], a3 = acc[i][3] * sc[i];
            #pragma unroll
            for (int c = 0; c < 32; c++) {
                float p = Ss[r0 + i][c];
                float4 v = *(const float4*)&Vs[c][d0];
                a0 += p * v.x; a1 += p * v.y; a2 += p * v.z; a3 += p * v.w;
            }
            acc[i][0] = a0; acc[i][1] = a1; acc[i][2] = a2; acc[i][3] = a3;
        }
        __syncthreads();
    }

    // epilogue: A[b, q, h*64 + d] = acc / (l + ghost[h])
    const int bb = bh >> 4, hh = bh & 15;
    const float gh = ghost[hh];
    #pragma unroll
    for (int i = 0; i < 4; i++) {
        int qq = q0 + r0 + i;
        float inv = 1.0f / (rl[i] + gh);
        float* dst = g_A + ((size_t)(bb * SEQ + qq)) * EMB + hh * HDIM + tx * 4;
        dst[0] = acc[i][0] * inv;
        dst[1] = acc[i][1] * inv;
        dst[2] = acc[i][2] * inv;
        dst[3] = acc[i][3] * inv;
    }
}

// ============================================================================
extern "C" void kernel_launch(void* const* d_in, const int* in_sizes, int n_in,
                              void* d_out, int out_size)
{
    const float* X      = (const float*)d_in[0];  // [2,2048,1024]
    const float* Wqkv_w = (const float*)d_in[1];  // [3072,1024]
    const float* Wqkv_b = (const float*)d_in[2];  // [3072]
    const float* Wo_w   = (const float*)d_in[3];  // [1024,1024]
    const float* Wo_b   = (const float*)d_in[4];  // [1024]
    const float* ghost  = (const float*)d_in[5];  // [16]
    float* out = (float*)d_out;

    dim3 g1(3072 / 128, (BATCH * SEQ) / 128);     // 24 x 32
    qkv_gemm_kernel<<<g1, 256>>>(X, Wqkv_w, Wqkv_b);

    dim3 g2(SEQ / 64, BATCH * NHEAD);             // 32 x 32
    attn_kernel<<<g2, 256>>>(ghost);

    dim3 g3(EMB / 128, (BATCH * SEQ) / 128);      // 8 x 32
    out_gemm_kernel<<<g3, 256>>>(Wo_w, Wo_b, out);
}

// round 10
// speedup vs baseline: 1.1035x; 1.1035x over previous
#include <cuda_runtime.h>
#include <math.h>

#define BATCH 2
#define SEQ   2048
#define EMB   1024
#define NHEAD 16
#define HDIM  64
#define NEGF  1e30f

typedef unsigned long long u64;

// Scratch (allocation-free rule: __device__ globals)
__device__ float g_Q[BATCH * NHEAD * SEQ * HDIM];   // [B,H,S,D]
__device__ float g_K[BATCH * NHEAD * SEQ * HDIM];   // [B,H,S,D]
__device__ float g_V[BATCH * NHEAD * SEQ * HDIM];   // [B,H,S,D]
__device__ float g_A[BATCH * SEQ * EMB];            // [B,S,H*D]

// ---- packed f32x2 helpers (Blackwell dual-FMA datapath, PTX ISA 8.6) ------
__device__ __forceinline__ u64 pk2(float x, float y) {
    u64 r; asm("mov.b64 %0, {%1, %2};" : "=l"(r) : "f"(x), "f"(y)); return r;
}
__device__ __forceinline__ float2 up2(u64 v) {
    float2 f; asm("mov.b64 {%0, %1}, %2;" : "=f"(f.x), "=f"(f.y) : "l"(v)); return f;
}
#define FFMA2(C, A, B) asm("fma.rn.f32x2 %0, %1, %2, %0;" : "+l"(C) : "l"(A), "l"(B))
#define FMUL2(D, A, B) asm("mul.rn.f32x2 %0, %1, %2;" : "=l"(D) : "l"(A), "l"(B))

// ============================================================================
// GEMM-NT 128x128x16, 256 threads, 8x8 per-thread tile (as 8x4 f32x2 pairs),
// double-buffered smem + register prefetch, one __syncthreads per K-chunk.
// C[m][n] = sum_k A[m][k] * B[n][k]
// ============================================================================

// ---- QKV projection: X[4096,1024] @ Wqkv[3072,1024]^T + b, scatter to Q/K/V
__global__ __launch_bounds__(256)
void qkv_gemm_kernel(const float* __restrict__ X,
                     const float* __restrict__ W,
                     const float* __restrict__ bias)
{
    __shared__ float As[2][16][132];
    __shared__ float Bs[2][16][132];
    const int tid = threadIdx.x;
    const int tx = tid & 15, ty = tid >> 4;
    const int bm = blockIdx.y * 128, bn = blockIdx.x * 128;
    const int lrow = tid >> 2;
    const int lc4  = (tid & 3) << 2;

    u64 acc2[8][4];
    #pragma unroll
    for (int i = 0; i < 8; i++)
        #pragma unroll
        for (int j = 0; j < 4; j++) acc2[i][j] = 0ull;

    const float* pA0 = X + (size_t)(bm + lrow) * EMB + lc4;
    const float* pA1 = X + (size_t)(bm + lrow + 64) * EMB + lc4;
    const float* pB0 = W + (size_t)(bn + lrow) * EMB + lc4;
    const float* pB1 = W + (size_t)(bn + lrow + 64) * EMB + lc4;

    float4 ra0 = *(const float4*)pA0;
    float4 ra1 = *(const float4*)pA1;
    float4 rb0 = *(const float4*)pB0;
    float4 rb1 = *(const float4*)pB1;

    #pragma unroll 1
    for (int c = 0; c < EMB / 16; c++) {
        const int buf = c & 1;
        As[buf][lc4 + 0][lrow] = ra0.x; As[buf][lc4 + 1][lrow] = ra0.y;
        As[buf][lc4 + 2][lrow] = ra0.z; As[buf][lc4 + 3][lrow] = ra0.w;
        As[buf][lc4 + 0][lrow + 64] = ra1.x; As[buf][lc4 + 1][lrow + 64] = ra1.y;
        As[buf][lc4 + 2][lrow + 64] = ra1.z; As[buf][lc4 + 3][lrow + 64] = ra1.w;
        Bs[buf][lc4 + 0][lrow] = rb0.x; Bs[buf][lc4 + 1][lrow] = rb0.y;
        Bs[buf][lc4 + 2][lrow] = rb0.z; Bs[buf][lc4 + 3][lrow] = rb0.w;
        Bs[buf][lc4 + 0][lrow + 64] = rb1.x; Bs[buf][lc4 + 1][lrow + 64] = rb1.y;
        Bs[buf][lc4 + 2][lrow + 64] = rb1.z; Bs[buf][lc4 + 3][lrow + 64] = rb1.w;
        __syncthreads();

        if (c + 1 < EMB / 16) {
            const int o = (c + 1) * 16;
            ra0 = *(const float4*)(pA0 + o);
            ra1 = *(const float4*)(pA1 + o);
            rb0 = *(const float4*)(pB0 + o);
            rb1 = *(const float4*)(pB1 + o);
        }

        #pragma unroll
        for (int k = 0; k < 16; k++) {
            float4 a0 = *(const float4*)&As[buf][k][ty * 4];
            float4 a1 = *(const float4*)&As[buf][k][64 + ty * 4];
            float4 b0 = *(const float4*)&Bs[buf][k][tx * 4];
            float4 b1 = *(const float4*)&Bs[buf][k][64 + tx * 4];
            u64 bp0 = pk2(b0.x, b0.y), bp1 = pk2(b0.z, b0.w);
            u64 bp2 = pk2(b1.x, b1.y), bp3 = pk2(b1.z, b1.w);
            float a[8] = {a0.x, a0.y, a0.z, a0.w, a1.x, a1.y, a1.z, a1.w};
            #pragma unroll
            for (int i = 0; i < 8; i++) {
                u64 aa = pk2(a[i], a[i]);
                FFMA2(acc2[i][0], aa, bp0);
                FFMA2(acc2[i][1], aa, bp1);
                FFMA2(acc2[i][2], aa, bp2);
                FFMA2(acc2[i][3], aa, bp3);
            }
        }
    }

    #pragma unroll
    for (int i = 0; i < 8; i++) {
        int m = bm + ((i < 4) ? (ty * 4 + i) : (64 + ty * 4 + i - 4));
        int bb = m >> 11;
        int ss = m & (SEQ - 1);
        #pragma unroll
        for (int jp = 0; jp < 4; jp++) {
            int n = bn + ((jp < 2) ? (tx * 4 + jp * 2) : (64 + tx * 4 + (jp - 2) * 2));
            float2 cv = up2(acc2[i][jp]);
            cv.x += bias[n];
            cv.y += bias[n + 1];
            int w = n >> 10;
            int h = (n >> 6) & 15;
            int d = n & 63;
            float* dst = (w == 0) ? g_Q : (w == 1) ? g_K : g_V;
            *(float2*)&dst[(((size_t)(bb * NHEAD + h)) * SEQ + ss) * HDIM + d] = cv;
        }
    }
}

// ---- Output projection: A[4096,1024] @ Wo[1024,1024]^T + b -> out
__global__ __launch_bounds__(256)
void out_gemm_kernel(const float* __restrict__ W,
                     const float* __restrict__ bias,
                     float* __restrict__ out)
{
    __shared__ float As[2][16][132];
    __shared__ float Bs[2][16][132];
    const int tid = threadIdx.x;
    const int tx = tid & 15, ty = tid >> 4;
    const int bm = blockIdx.y * 128, bn = blockIdx.x * 128;
    const int lrow = tid >> 2;
    const int lc4  = (tid & 3) << 2;

    u64 acc2[8][4];
    #pragma unroll
    for (int i = 0; i < 8; i++)
        #pragma unroll
        for (int j = 0; j < 4; j++) acc2[i][j] = 0ull;

    const float* pA0 = g_A + (size_t)(bm + lrow) * EMB + lc4;
    const float* pA1 = g_A + (size_t)(bm + lrow + 64) * EMB + lc4;
    const float* pB0 = W + (size_t)(bn + lrow) * EMB + lc4;
    const float* pB1 = W + (size_t)(bn + lrow + 64) * EMB + lc4;

    float4 ra0 = *(const float4*)pA0;
    float4 ra1 = *(const float4*)pA1;
    float4 rb0 = *(const float4*)pB0;
    float4 rb1 = *(const float4*)pB1;

    #pragma unroll 1
    for (int c = 0; c < EMB / 16; c++) {
        const int buf = c & 1;
        As[buf][lc4 + 0][lrow] = ra0.x; As[buf][lc4 + 1][lrow] = ra0.y;
        As[buf][lc4 + 2][lrow] = ra0.z; As[buf][lc4 + 3][lrow] = ra0.w;
        As[buf][lc4 + 0][lrow + 64] = ra1.x; As[buf][lc4 + 1][lrow + 64] = ra1.y;
        As[buf][lc4 + 2][lrow + 64] = ra1.z; As[buf][lc4 + 3][lrow + 64] = ra1.w;
        Bs[buf][lc4 + 0][lrow] = rb0.x; Bs[buf][lc4 + 1][lrow] = rb0.y;
        Bs[buf][lc4 + 2][lrow] = rb0.z; Bs[buf][lc4 + 3][lrow] = rb0.w;
        Bs[buf][lc4 + 0][lrow + 64] = rb1.x; Bs[buf][lc4 + 1][lrow + 64] = rb1.y;
        Bs[buf][lc4 + 2][lrow + 64] = rb1.z; Bs[buf][lc4 + 3][lrow + 64] = rb1.w;
        __syncthreads();

        if (c + 1 < EMB / 16) {
            const int o = (c + 1) * 16;
            ra0 = *(const float4*)(pA0 + o);
            ra1 = *(const float4*)(pA1 + o);
            rb0 = *(const float4*)(pB0 + o);
            rb1 = *(const float4*)(pB1 + o);
        }

        #pragma unroll
        for (int k = 0; k < 16; k++) {
            float4 a0 = *(const float4*)&As[buf][k][ty * 4];
            float4 a1 = *(const float4*)&As[buf][k][64 + ty * 4];
            float4 b0 = *(const float4*)&Bs[buf][k][tx * 4];
            float4 b1 = *(const float4*)&Bs[buf][k][64 + tx * 4];
            u64 bp0 = pk2(b0.x, b0.y), bp1 = pk2(b0.z, b0.w);
            u64 bp2 = pk2(b1.x, b1.y), bp3 = pk2(b1.z, b1.w);
            float a[8] = {a0.x, a0.y, a0.z, a0.w, a1.x, a1.y, a1.z, a1.w};
            #pragma unroll
            for (int i = 0; i < 8; i++) {
                u64 aa = pk2(a[i], a[i]);
                FFMA2(acc2[i][0], aa, bp0);
                FFMA2(acc2[i][1], aa, bp1);
                FFMA2(acc2[i][2], aa, bp2);
                FFMA2(acc2[i][3], aa, bp3);
            }
        }
    }

    #pragma unroll
    for (int i = 0; i < 8; i++) {
        int m = bm + ((i < 4) ? (ty * 4 + i) : (64 + ty * 4 + i - 4));
        #pragma unroll
        for (int jp = 0; jp < 4; jp++) {
            int n = bn + ((jp < 2) ? (tx * 4 + jp * 2) : (64 + tx * 4 + (jp - 2) * 2));
            float2 cv = up2(acc2[i][jp]);
            cv.x += bias[n];
            cv.y += bias[n + 1];
            *(float2*)&out[(size_t)m * EMB + n] = cv;
        }
    }
}

// ============================================================================
// Flash attention, causal, fp32, f32x2 math. Block = 64 q; key tiles of 32.
// 256 threads as 16x16; per-thread: S tile 4x2, O tile 4x4 (2 pairs).
// Online-softmax state in registers (16-lane row groups, shfl reductions).
// ============================================================================
__global__ __launch_bounds__(256)
void attn_kernel(const float* __restrict__ ghost)
{
    __shared__ float Qs[64][68];
    __shared__ float Ks[32][68];
    __shared__ float Vs[32][68];
    __shared__ float Ss[64][33];

    const int qi = blockIdx.x;          // 0..31
    const int bh = blockIdx.y;          // 0..31
    const int tid = threadIdx.x;
    const int tx = tid & 15, ty = tid >> 4;
    const int r0 = ty * 4;
    const int q0 = qi * 64;

    const float* Qb = g_Q + (size_t)bh * SEQ * HDIM;
    const float* Kb = g_K + (size_t)bh * SEQ * HDIM;
    const float* Vb = g_V + (size_t)bh * SEQ * HDIM;

    for (int i = tid; i < 64 * 16; i += 256) {
        int r = i >> 4, c4 = (i & 15) << 2;
        *(float4*)&Qs[r][c4] = *(const float4*)&Qb[(size_t)(q0 + r) * HDIM + c4];
    }

    u64 acc2[4][2];
    float rm[4], rl[4];
    #pragma unroll
    for (int i = 0; i < 4; i++) {
        rm[i] = -NEGF; rl[i] = 0.f;
        acc2[i][0] = 0ull; acc2[i][1] = 0ull;
    }

    __syncthreads();

    const int nkt = 2 * qi + 2;
    #pragma unroll 1
    for (int kt = 0; kt < nkt; kt++) {
        const int k0 = kt * 32;
        for (int i = tid; i < 32 * 16; i += 256) {
            int r = i >> 4, c4 = (i & 15) << 2;
            *(float4*)&Ks[r][c4] = *(const float4*)&Kb[(size_t)(k0 + r) * HDIM + c4];
            *(float4*)&Vs[r][c4] = *(const float4*)&Vb[(size_t)(k0 + r) * HDIM + c4];
        }
        __syncthreads();

        // S = Q K^T (pairs along d, horizontal add at end)
        u64 s2[4][2];
        #pragma unroll
        for (int i = 0; i < 4; i++) { s2[i][0] = 0ull; s2[i][1] = 0ull; }
        #pragma unroll
        for (int d4 = 0; d4 < 64; d4 += 4) {
            float4 kv0 = *(const float4*)&Ks[tx][d4];
            float4 kv1 = *(const float4*)&Ks[tx + 16][d4];
            u64 k0a = pk2(kv0.x, kv0.y), k0b = pk2(kv0.z, kv0.w);
            u64 k1a = pk2(kv1.x, kv1.y), k1b = pk2(kv1.z, kv1.w);
            #pragma unroll
            for (int i = 0; i < 4; i++) {
                float4 qv = *(const float4*)&Qs[r0 + i][d4];
                u64 qa = pk2(qv.x, qv.y), qb = pk2(qv.z, qv.w);
                FFMA2(s2[i][0], qa, k0a);
                FFMA2(s2[i][0], qb, k0b);
                FFMA2(s2[i][1], qa, k1a);
                FFMA2(s2[i][1], qb, k1b);
            }
        }
        float s[4][2];
        #pragma unroll
        for (int i = 0; i < 4; i++) {
            float2 t0 = up2(s2[i][0]);
            float2 t1 = up2(s2[i][1]);
            s[i][0] = t0.x + t0.y;
            s[i][1] = t1.x + t1.y;
        }
        const bool need_mask = (kt >= 2 * qi);
        #pragma unroll
        for (int i = 0; i < 4; i++) {
            int qq = q0 + r0 + i;
            #pragma unroll
            for (int j = 0; j < 2; j++) {
                int kk = k0 + tx + 16 * j;
                float v = s[i][j] * 0.125f;
                if (need_mask && kk > qq) v = -NEGF;
                s[i][j] = v;
            }
        }

        // register online softmax; row group = 16 lanes
        float sc[4];
        #pragma unroll
        for (int i = 0; i < 4; i++) {
            float t = fmaxf(s[i][0], s[i][1]);
            t = fmaxf(t, __shfl_xor_sync(0xffffffffu, t, 1));
            t = fmaxf(t, __shfl_xor_sync(0xffffffffu, t, 2));
            t = fmaxf(t, __shfl_xor_sync(0xffffffffu, t, 4));
            t = fmaxf(t, __shfl_xor_sync(0xffffffffu, t, 8));
            float mn = fmaxf(rm[i], t);
            sc[i] = __expf(rm[i] - mn);
            rm[i] = mn;
            float p0 = __expf(s[i][0] - mn);
            float p1 = __expf(s[i][1] - mn);
            float ps = p0 + p1;
            ps += __shfl_xor_sync(0xffffffffu, ps, 1);
            ps += __shfl_xor_sync(0xffffffffu, ps, 2);
            ps += __shfl_xor_sync(0xffffffffu, ps, 4);
            ps += __shfl_xor_sync(0xffffffffu, ps, 8);
            rl[i] = rl[i] * sc[i] + ps;
            Ss[r0 + i][tx] = p0;
            Ss[r0 + i][tx + 16] = p1;
        }
        __syncthreads();

        // O = O*sc + P @ V (pairs along d)
        const int d0 = tx * 4;
        #pragma unroll
        for (int i = 0; i < 4; i++) {
            u64 scp = pk2(sc[i], sc[i]);
            FMUL2(acc2[i][0], acc2[i][0], scp);
            FMUL2(acc2[i][1], acc2[i][1], scp);
        }
        #pragma unroll
        for (int c = 0; c < 32; c++) {
            float4 v = *(const float4*)&Vs[c][d0];
            u64 va = pk2(v.x, v.y), vb = pk2(v.z, v.w);
            #pragma unroll
            for (int i = 0; i < 4; i++) {
                float p = Ss[r0 + i][c];
                u64 pp = pk2(p, p);
                FFMA2(acc2[i][0], pp, va);
                FFMA2(acc2[i][1], pp, vb);
            }
        }
        __syncthreads();
    }

    // epilogue: A[b, q, h*64 + d] = acc / (l + ghost[h])
    const int bb = bh >> 4, hh = bh & 15;
    const float gh = ghost[hh];
    #pragma unroll
    for (int i = 0; i < 4; i++) {
        int qq = q0 + r0 + i;
        float inv = 1.0f / (rl[i] + gh);
        float2 lo = up2(acc2[i][0]);
        float2 hi = up2(acc2[i][1]);
        float* dst = g_A + ((size_t)(bb * SEQ + qq)) * EMB + hh * HDIM + tx * 4;
        dst[0] = lo.x * inv;
        dst[1] = lo.y * inv;
        dst[2] = hi.x * inv;
        dst[3] = hi.y * inv;
    }
}

// ============================================================================
extern "C" void kernel_launch(void* const* d_in, const int* in_sizes, int n_in,
                              void* d_out, int out_size)
{
    const float* X      = (const float*)d_in[0];  // [2,2048,1024]
    const float* Wqkv_w = (const float*)d_in[1];  // [3072,1024]
    const float* Wqkv_b = (const float*)d_in[2];  // [3072]
    const float* Wo_w   = (const float*)d_in[3];  // [1024,1024]
    const float* Wo_b   = (const float*)d_in[4];  // [1024]
    const float* ghost  = (const float*)d_in[5];  // [16]
    float* out = (float*)d_out;

    dim3 g1(3072 / 128, (BATCH * SEQ) / 128);     // 24 x 32
    qkv_gemm_kernel<<<g1, 256>>>(X, Wqkv_w, Wqkv_b);

    dim3 g2(SEQ / 64, BATCH * NHEAD);             // 32 x 32
    attn_kernel<<<g2, 256>>>(ghost);

    dim3 g3(EMB / 128, (BATCH * SEQ) / 128);      // 8 x 32
    out_gemm_kernel<<<g3, 256>>>(Wo_w, Wo_b, out);
}